// round 9
// baseline (speedup 1.0000x reference)
#include <cuda_runtime.h>

// ---------------- Problem constants ----------------
#define NBOX 8000          // 5 anchors * 40 * 40
#define HW 40
#define NCLS 20
#define CHSTRIDE (HW*HW)   // 1600 floats between channels
#define STRIDEPX 8.0f      // 320 / 40

#define JC 16
#define CHUNKMAX 500       // ceil(8000/16)
#define IGROUPS 32         // 32*256 = 8192 >= NV

#define MMASK 256          // mask-matrix fast-path capacity (expected M ~ 200)
#define NW 8               // 256/32 words per mask row
#define CAP 768            // shared box capacity (mid path)

// ---------------- Scratch (device globals, no allocation) ----------------
__device__ float              d_dec6[NBOX * 6];       // decoded rows, original index order
__device__ unsigned long long d_vkey[NBOX];           // valid-compacted keys
__device__ unsigned char      d_vcode[NBOX];          // valid-compacted class
__device__ int                d_vidx[NBOX];           // valid-compacted original index
__device__ int                d_nv;                   // number of valid boxes (accumulator)
__device__ int                d_nv2;                  // snapshot for k_nms (set by k_rank)
__device__ unsigned           d_partial[JC * NBOX];   // packed: rank | cls_rank<<16
__device__ int                d_cand[NCLS * NBOX];    // fallback only: r | orig<<16 at slot rc

// ---------------- K1: decode + valid compaction + zero output ----------------
__global__ void k_decode(const float* __restrict__ x, const float* __restrict__ anchors,
                         float* __restrict__ out) {
    int i = blockIdx.x * blockDim.x + threadIdx.x;
    if (i < NBOX * 6) out[i] = 0.0f;      // output pre-zero (poisoned before timing)
    if (i >= NBOX) return;

    int a   = i / (HW * HW);
    int rem = i - a * (HW * HW);
    int gy  = rem / HW;
    int gx  = rem - gy * HW;
    int base = ((a * 25) * HW + gy) * HW + gx;

    float t0 = x[base + 0 * CHSTRIDE];
    float t1 = x[base + 1 * CHSTRIDE];
    float t2 = x[base + 2 * CHSTRIDE];
    float t3 = x[base + 3 * CHSTRIDE];
    float t4 = x[base + 4 * CHSTRIDE];

    float tx   = 1.0f / (1.0f + expf(-t0));
    float ty   = 1.0f / (1.0f + expf(-t1));
    float conf = 1.0f / (1.0f + expf(-t4));

    float aw = anchors[a * 2 + 0];
    float ah = anchors[a * 2 + 1];

    float bx = (tx + (float)gx) * STRIDEPX;
    float by = (ty + (float)gy) * STRIDEPX;
    float bw = expf(t2) * aw * STRIDEPX;
    float bh = expf(t3) * ah * STRIDEPX;

    // argmax over class logits (sigmoid monotone; '>' keeps first occurrence like jnp.argmax)
    float best = x[base + 5 * CHSTRIDE];
    int bc = 0;
#pragma unroll
    for (int c = 1; c < NCLS; c++) {
        float t = x[base + (5 + c) * CHSTRIDE];
        if (t > best) { best = t; bc = c; }
    }

    d_dec6[i * 6 + 0] = bx;
    d_dec6[i * 6 + 1] = by;
    d_dec6[i * 6 + 2] = bw;
    d_dec6[i * 6 + 3] = bh;
    d_dec6[i * 6 + 4] = conf;
    d_dec6[i * 6 + 5] = (float)bc;

    // valid (conf>0.5 <=> logit>0): append to compacted list.
    // Slot order nondeterministic; ranks below are value-based -> deterministic output.
    if (t4 > 0.0f) {
        int slot = atomicAdd(&d_nv, 1);
        unsigned u = __float_as_uint(conf);
        d_vkey[slot]  = ((unsigned long long)(~u) << 32) | (unsigned long long)(unsigned)i;
        d_vcode[slot] = (unsigned char)bc;
        d_vidx[slot]  = i;
    }
}

// ---------------- K2: chunked rank over valid boxes (+ snapshot NV) ----------------
__global__ void k_rank() {
    __shared__ unsigned long long sk[CHUNKMAX];
    __shared__ unsigned char     sc[CHUNKMAX];
    int NV = d_nv;
    if (blockIdx.x == 0 && threadIdx.x == 0) d_nv2 = NV;   // snapshot for k_nms
    int CS = (NV + JC - 1) / JC;
    int g = blockIdx.x / JC;
    int c = blockIdx.x - g * JC;
    int j0 = c * CS;
    int cnt = NV - j0; if (cnt > CS) cnt = CS; if (cnt < 0) cnt = 0;
    for (int t = threadIdx.x; t < cnt; t += 256) {
        sk[t] = d_vkey[j0 + t];
        sc[t] = d_vcode[j0 + t];
    }
    __syncthreads();
    int i = g * 256 + threadIdx.x;
    if (i < NV) {
        unsigned long long my = d_vkey[i];
        unsigned char myc = d_vcode[i];
        unsigned acc = 0;
#pragma unroll 4
        for (int j = 0; j < cnt; j++) {
            bool lt = sk[j] < my;
            acc += lt ? (1u + (((sc[j] == myc) ? 1u : 0u) << 16)) : 0u;
        }
        d_partial[c * NBOX + i] = acc;
    }
}

// IoU >= 0.5 <=> 2*inter >= union (division-free)
__device__ __forceinline__ bool sup_test(float xi1, float yi1, float xi2, float yi2, float ai,
                                         float xj1, float yj1, float xj2, float yj2, float aj) {
    float iw = fmaxf(fminf(xi2, xj2) - fmaxf(xi1, xj1), 0.0f);
    float ih = fmaxf(fminf(yi2, yj2) - fmaxf(yi1, yj1), 0.0f);
    float inter = iw * ih;
    float denom = ai + aj - inter + 1e-6f;
    return 2.0f * inter >= denom;
}

__device__ __forceinline__ void emit_box(float* out, int r, int orig) {
#pragma unroll
    for (int k = 0; k < 6; k++) out[6 * r + k] = d_dec6[orig * 6 + k];
}

// ---------------- K3: fused gather + per-class NMS + output ----------------
__global__ void k_nms(float* __restrict__ out) {
    __shared__ int      sps[CAP];               // slot rc -> output row (global rank)
    __shared__ int      sor[CAP];               // slot rc -> original index
    __shared__ float    sx1[CAP], sy1[CAP], sx2[CAP], sy2[CAP], sar[CAP];
    __shared__ unsigned smask[MMASK * NW];
    __shared__ unsigned srow[NW];
    __shared__ unsigned skw[NW];
    __shared__ int      sM;

    int c    = blockIdx.x;
    int tid  = threadIdx.x;
    int lane = tid & 31;
    int warp = tid >> 5;
    int NV   = d_nv2;

    if (c == 0 && tid == 0) d_nv = 0;   // reset accumulator for next graph replay
    if (tid == 0) sM = 0;
    if (tid < NW) srow[tid] = 0;
    __syncthreads();

    // ---- gather: scan valid slots, compute ranks from partials, place at slot rc ----
    for (int v = tid; v < NV; v += 512) {
        if (d_vcode[v] == (unsigned char)c) {
            unsigned s = 0;
#pragma unroll
            for (int k = 0; k < JC; k++) s += d_partial[k * NBOX + v];
            int r  = (int)(s & 0xffffu);    // global rank (valid sort above invalid)
            int rc = (int)(s >> 16);        // class rank (unique within class)
            int orig = d_vidx[v];
            atomicAdd(&sM, 1);
            d_cand[c * NBOX + rc] = r | (orig << 16);   // for fallback path
            if (rc < CAP) {
                float cx = d_dec6[orig * 6 + 0];
                float cy = d_dec6[orig * 6 + 1];
                float w  = d_dec6[orig * 6 + 2];
                float h  = d_dec6[orig * 6 + 3];
                float x1 = cx - 0.5f * w, y1 = cy - 0.5f * h;
                float x2 = cx + 0.5f * w, y2 = cy + 0.5f * h;
                sps[rc] = r; sor[rc] = orig;
                sx1[rc] = x1; sy1[rc] = y1; sx2[rc] = x2; sy2[rc] = y2;
                sar[rc] = fabsf((x2 - x1) * (y2 - y1));
            }
        }
    }
    __syncthreads();
    int M = sM;
    if (M == 0) return;

    if (M <= MMASK) {
        // ---- ballot mask fill: one warp per row ----
        int nw = (M + 31) >> 5;
        for (int i = warp; i < M; i += 16) {
            float xi1 = sx1[i], yi1 = sy1[i], xi2 = sx2[i], yi2 = sy2[i], ai = sar[i];
            int wq0 = (i + 1) >> 5;
            unsigned rowany = 0;
            if (lane == 0)
                for (int q = 0; q < wq0; q++) smask[i * NW + q] = 0;
            for (int wq = wq0; wq < nw; wq++) {
                int j = (wq << 5) + lane;
                bool s = (j > i) && (j < M) &&
                         sup_test(xi1, yi1, xi2, yi2, ai,
                                  sx1[j], sy1[j], sx2[j], sy2[j], sar[j]);
                unsigned bits = __ballot_sync(0xffffffffu, s);
                if (lane == 0) smask[i * NW + wq] = bits;
                rowany |= bits;
            }
            if (lane == 0 && rowany) atomicOr(&srow[i >> 5], 1u << (i & 31));
        }
        __syncthreads();

        // ---- single-thread register sweep (only surviving suppressing pivots) ----
        if (tid == 0) {
            unsigned kw[NW];
#pragma unroll
            for (int q = 0; q < NW; q++) {
                int lo = q * 32;
                unsigned v = 0;
                if (lo < M) {
                    int rem = M - lo;
                    v = (rem >= 32) ? 0xffffffffu : ((1u << rem) - 1u);
                }
                kw[q] = v;
            }
            int nwl = (M + 31) >> 5;
            for (int w = 0; w < nwl; w++) {
                unsigned active = kw[w] & srow[w];
                while (active) {
                    int b = __ffs(active) - 1;
                    int i = w * 32 + b;
#pragma unroll
                    for (int q = 0; q < NW; q++)
                        kw[q] &= ~smask[i * NW + q];   // rows hold only j>i bits
                    active = kw[w] & srow[w] & (0xfffffffeu << b);
                }
            }
#pragma unroll
            for (int q = 0; q < NW; q++) skw[q] = kw[q];
        }
        __syncthreads();
        for (int t = tid; t < M; t += 512)
            if ((skw[t >> 5] >> (t & 31)) & 1u) emit_box(out, sps[t], sor[t]);
    } else if (M <= CAP) {
        // ---- mid path: pivot loop in shared ----
        unsigned char* skbyte = (unsigned char*)smask;   // 8192 bytes >= CAP
        for (int t = tid; t < M; t += 512) skbyte[t] = 1;
        __syncthreads();
        for (int i = 0; i < M - 1; i++) {
            __syncthreads();
            if (!skbyte[i]) continue;
            float xi1 = sx1[i], yi1 = sy1[i], xi2 = sx2[i], yi2 = sy2[i], ai = sar[i];
            for (int j = i + 1 + tid; j < M; j += 512) {
                if (!skbyte[j]) continue;
                if (sup_test(xi1, yi1, xi2, yi2, ai,
                             sx1[j], sy1[j], sx2[j], sy2[j], sar[j]))
                    skbyte[j] = 0;
            }
        }
        __syncthreads();
        for (int t = tid; t < M; t += 512)
            if (skbyte[t]) emit_box(out, sps[t], sor[t]);
    } else {
        // ---- fallback (M > CAP, never expected): global pivot loop via d_cand ----
        unsigned char* skbyte = (unsigned char*)sx1;     // 15360 bytes >= 8000 >= M
        for (int t = tid; t < M; t += 512) skbyte[t] = 1;
        __syncthreads();
        for (int i = 0; i < M - 1; i++) {
            __syncthreads();
            if (!skbyte[i]) continue;
            int pi = d_cand[c * NBOX + i];
            int oi = pi >> 16;
            float cx = d_dec6[oi * 6 + 0], cy = d_dec6[oi * 6 + 1];
            float w  = d_dec6[oi * 6 + 2], h  = d_dec6[oi * 6 + 3];
            float xi1 = cx - 0.5f * w, yi1 = cy - 0.5f * h;
            float xi2 = cx + 0.5f * w, yi2 = cy + 0.5f * h;
            float ai = fabsf((xi2 - xi1) * (yi2 - yi1));
            for (int j = i + 1 + tid; j < M; j += 512) {
                if (!skbyte[j]) continue;
                int pj = d_cand[c * NBOX + j];
                int oj = pj >> 16;
                float cxj = d_dec6[oj * 6 + 0], cyj = d_dec6[oj * 6 + 1];
                float wj  = d_dec6[oj * 6 + 2], hj  = d_dec6[oj * 6 + 3];
                float xj1 = cxj - 0.5f * wj, yj1 = cyj - 0.5f * hj;
                float xj2 = cxj + 0.5f * wj, yj2 = cyj + 0.5f * hj;
                float aj = fabsf((xj2 - xj1) * (yj2 - yj1));
                if (sup_test(xi1, yi1, xi2, yi2, ai, xj1, yj1, xj2, yj2, aj))
                    skbyte[j] = 0;
            }
        }
        __syncthreads();
        for (int t = tid; t < M; t += 512) {
            if (skbyte[t]) {
                int p = d_cand[c * NBOX + t];
                emit_box(out, p & 0xffff, p >> 16);
            }
        }
    }
}

// ---------------- launch ----------------
extern "C" void kernel_launch(void* const* d_in, const int* in_sizes, int n_in,
                              void* d_out, int out_size) {
    const float* x;
    const float* anchors;
    if (in_sizes[0] == 10) { anchors = (const float*)d_in[0]; x = (const float*)d_in[1]; }
    else                   { x = (const float*)d_in[0]; anchors = (const float*)d_in[1]; }
    float* out = (float*)d_out;

    k_decode <<<(NBOX * 6 + 255) / 256, 256>>>(x, anchors, out);
    k_rank   <<<IGROUPS * JC, 256>>>();
    k_nms    <<<NCLS, 512>>>(out);
}